// round 8
// baseline (speedup 1.0000x reference)
#include <cuda_runtime.h>
#include <cuda_bf16.h>

// MotionPrimitiveDecoder: logits[b,n,t,a] = dot(df[b,n,t,a,:], z[b,n,:]) + cd[t,a] - mean_fa(cd[t,:])
// where cd = ctx_features . u_ctx_w.  The frenet/polyline projection term is constant
// across (t,a) for fixed (b,n) and cancels exactly in u - u_mean, so
// map_polylines / idx / pts are never read.
//
// Shapes: B=32, N=64, T=40, A=6, Z=64, C=3.
//
// R8: R5 fused structure + 6-deep rolling pipeline + launch_bounds(256,5) to pin
//     regs <= 51 (keeps 5 CTAs/SM) + __ldcs evict-first streaming loads for df.

#define B_DIM 32
#define N_DIM 64
#define T_DIM 40
#define A_DIM 6
#define Z_DIM 64
#define TA_DIM (T_DIM * A_DIM)   // 240
#define DEPTH 6

__global__ __launch_bounds__(256, 5) void mpd_kernel(
    const float* __restrict__ z,     // [BN,Z]
    const float* __restrict__ df,    // [BN,TA,Z]
    const float* __restrict__ ctx,   // [BN,TA,3]
    const int*   __restrict__ fa,    // [BN,TA]
    const float* __restrict__ w,     // [3]
    float* __restrict__ out)         // [BN,TA]
{
    __shared__ float4 z4_s[Z_DIM / 4];
    __shared__ float  cd_s[TA_DIM];
    __shared__ float  mean_s[T_DIM];

    const int bn  = blockIdx.x;              // 0 .. B*N-1
    const int tid = threadIdx.x;

    const long zb  = (long)bn * Z_DIM;
    const long dfb = (long)bn * TA_DIM * Z_DIM;
    const long cb  = (long)bn * TA_DIM * 3;
    const long fb  = (long)bn * TA_DIM;

    const int warp = tid >> 5;
    const int lane = tid & 31;
    const int half = lane >> 4;
    const int hl   = lane & 15;
    const int row0 = warp * 2 + half;

    // df pointer for this thread; consecutive slots stride 16 rows = 256 float4
    const float4* dfp = (const float4*)(df + dfb) + (long)row0 * 16 + hl;

    // ---- prime DEPTH streaming loads before the prologue (DRAM busy from cycle 0).
    //      __ldcs: evict-first, df has zero reuse -> don't churn L2. ----
    float4 v[DEPTH];
    #pragma unroll
    for (int j = 0; j < DEPTH; j++) v[j] = __ldcs(dfp + (long)j * 256);

    // ---- prologue (hidden in the load shadow) ----
    if (tid < Z_DIM / 4) z4_s[tid] = ((const float4*)(z + zb))[tid];

    const float w0 = __ldg(w), w1 = __ldg(w + 1), w2 = __ldg(w + 2);

    if (tid < TA_DIM) {
        const float* c = ctx + cb + (long)tid * 3;
        cd_s[tid] = c[0] * w0 + c[1] * w1 + c[2] * w2;
    }
    __syncthreads();

    if (tid < T_DIM) {
        const int* f = fa + fb + tid * A_DIM;
        float s_all = 0.f, s_f = 0.f;
        int cnt = 0;
        #pragma unroll
        for (int a = 0; a < A_DIM; a++) {
            float cda = cd_s[tid * A_DIM + a];
            s_all += cda;
            if (f[a]) { s_f += cda; cnt++; }
        }
        mean_s[tid] = cnt ? (s_f / (float)cnt) : (s_all / (float)A_DIM);
    }
    __syncthreads();

    const float4 zv = z4_s[hl];

    // ---- rolling pipeline: reduce slot j, immediately refill with row j+DEPTH ----
    #pragma unroll
    for (int j = 0; j < 15; j++) {
        const int ta = j * 16 + row0;
        const float4 x = v[j % DEPTH];

        if (j + DEPTH < 15) {
            v[j % DEPTH] = __ldcs(dfp + (long)(j + DEPTH) * 256);
        }

        float p = x.x * zv.x + x.y * zv.y + x.z * zv.z + x.w * zv.w;
        p += __shfl_xor_sync(0xFFFFFFFFu, p, 1);
        p += __shfl_xor_sync(0xFFFFFFFFu, p, 2);
        p += __shfl_xor_sync(0xFFFFFFFFu, p, 4);
        p += __shfl_xor_sync(0xFFFFFFFFu, p, 8);

        if (hl == 0) {
            out[fb + ta] = p + cd_s[ta] - mean_s[ta / A_DIM];
        }
    }
}

extern "C" void kernel_launch(void* const* d_in, const int* in_sizes, int n_in,
                              void* d_out, int out_size) {
    // metadata order: map_polylines, idx, pts, z, decision_features,
    //                 ctx_features, feasible_actions, u_ctx_w, u_ctx_b
    const float* z   = (const float*)d_in[3];
    const float* df  = (const float*)d_in[4];
    const float* ctx = (const float*)d_in[5];
    const int*   fa  = (const int*)d_in[6];
    const float* w   = (const float*)d_in[7];
    float* out = (float*)d_out;

    mpd_kernel<<<B_DIM * N_DIM, 256>>>(z, df, ctx, fa, w, out);
}

// round 9
// speedup vs baseline: 1.0837x; 1.0837x over previous
#include <cuda_runtime.h>
#include <cuda_bf16.h>

// MotionPrimitiveDecoder: logits[b,n,t,a] = dot(df[b,n,t,a,:], z[b,n,:]) + cd[t,a] - mean_fa(cd[t,:])
// where cd = ctx_features . u_ctx_w.  The frenet/polyline projection term is constant
// across (t,a) for fixed (b,n) and cancels exactly in u - u_mean, so
// map_polylines / idx / pts are never read.
//
// Shapes: B=32, N=64, T=40, A=6, Z=64, C=3.
//
// R9: warp-autonomous fused kernel. Each warp owns 30 contiguous rows = exactly
//     5 complete t-groups, so the feasibility-masked mean is computed entirely
//     with warp shuffles: NO smem, NO __syncthreads. Streaming = rolling 5-deep
//     pipeline, half-warp per row, plain float4 loads (no __ldcs, no reg pin).

#define B_DIM 32
#define N_DIM 64
#define T_DIM 40
#define A_DIM 6
#define Z_DIM 64
#define TA_DIM (T_DIM * A_DIM)   // 240
#define ROWS_PER_WARP 30         // 5 t-groups of 6 actions
#define DEPTH 5
#define FULL 0xFFFFFFFFu

__global__ __launch_bounds__(256) void mpd_kernel(
    const float* __restrict__ z,     // [BN,Z]
    const float* __restrict__ df,    // [BN,TA,Z]
    const float* __restrict__ ctx,   // [BN,TA,3]
    const int*   __restrict__ fa,    // [BN,TA]
    const float* __restrict__ w,     // [3]
    float* __restrict__ out)         // [BN,TA]
{
    const int bn   = blockIdx.x;             // 0 .. B*N-1
    const int tid  = threadIdx.x;
    const int warp = tid >> 5;
    const int lane = tid & 31;
    const int half = lane >> 4;              // row parity within the warp's pair
    const int hl   = lane & 15;              // float4 index within the row

    const long dfb = (long)bn * TA_DIM * Z_DIM;
    const long fb  = (long)bn * TA_DIM;
    const int  R0  = warp * ROWS_PER_WARP;   // first row owned by this warp

    // df pointer: slot j covers rows R0 + 2j + half, each row = 16 float4
    const float4* dfp = (const float4*)(df + dfb) + ((long)(R0 + half) * 16 + hl);

    // ---- prime DEPTH streaming loads first: DRAM busy from cycle 0,
    //      the entire bias phase below runs in their shadow ----
    float4 v[DEPTH];
    #pragma unroll
    for (int j = 0; j < DEPTH; j++) v[j] = dfp[(long)j * 32];   // +2 rows per slot

    // z directly from gmem (256B per bn, broadcast across half-warps / warps)
    const float4 zv = ((const float4*)(z + (long)bn * Z_DIM))[hl];

    // ---- warp-local bias: lane l (<30) owns row R0+l ----
    const float w0 = __ldg(w), w1 = __ldg(w + 1), w2 = __ldg(w + 2);

    const int lrow = (lane < ROWS_PER_WARP) ? lane : (ROWS_PER_WARP - 1);
    const float* c = ctx + ((long)(fb + R0 + lrow)) * 3;
    const float cd = c[0] * w0 + c[1] * w1 + c[2] * w2;
    const int   f  = fa[fb + R0 + lrow];

    // group of 6 lanes = one t; segmented masked mean via shuffles
    const int gbase = (lrow / A_DIM) * A_DIM;
    float s_all = 0.f, s_f = 0.f;
    int cnt = 0;
    #pragma unroll
    for (int k = 0; k < A_DIM; k++) {
        const float cdk = __shfl_sync(FULL, cd, gbase + k);
        const int   fk  = __shfl_sync(FULL, f,  gbase + k);
        s_all += cdk;
        if (fk) { s_f += cdk; cnt++; }
    }
    const float mean = cnt ? (s_f / (float)cnt) : (s_all / (float)A_DIM);
    const float bias = cd - mean;            // valid for lanes 0..29

    // ---- streaming: rolling pipeline, reduce slot j, refill slot j+DEPTH ----
    #pragma unroll
    for (int j = 0; j < 15; j++) {
        const float4 x = v[j % DEPTH];

        if (j + DEPTH < 15) {
            v[j % DEPTH] = dfp[(long)(j + DEPTH) * 32];
        }

        // broadcast this slot's bias (row index within warp = 2j + half)
        const float bb = __shfl_sync(FULL, bias, 2 * j + half);

        float p = x.x * zv.x + x.y * zv.y + x.z * zv.z + x.w * zv.w;
        p += __shfl_xor_sync(FULL, p, 1);
        p += __shfl_xor_sync(FULL, p, 2);
        p += __shfl_xor_sync(FULL, p, 4);
        p += __shfl_xor_sync(FULL, p, 8);

        if (hl == 0) {
            out[fb + R0 + 2 * j + half] = p + bb;
        }
    }
}

extern "C" void kernel_launch(void* const* d_in, const int* in_sizes, int n_in,
                              void* d_out, int out_size) {
    // metadata order: map_polylines, idx, pts, z, decision_features,
    //                 ctx_features, feasible_actions, u_ctx_w, u_ctx_b
    const float* z   = (const float*)d_in[3];
    const float* df  = (const float*)d_in[4];
    const float* ctx = (const float*)d_in[5];
    const int*   fa  = (const int*)d_in[6];
    const float* w   = (const float*)d_in[7];
    float* out = (float*)d_out;

    mpd_kernel<<<B_DIM * N_DIM, 256>>>(z, df, ctx, fa, w, out);
}